// round 4
// baseline (speedup 1.0000x reference)
#include <cuda_runtime.h>
#include <math.h>

#define S_    2048
#define DM_   768
#define H_    12
#define DK_   64
#define FEAT_ 128
#define J_    4095   /* 2S-1 */

// ---------------- scratch (static device globals; referenced ONLY in device code) --
__device__ float g_qh[H_*S_*DK_];
__device__ float g_kh[H_*S_*DK_];
__device__ float g_vh[H_*S_*DK_];
__device__ float g_pe[J_*DM_];
__device__ float g_rk[H_*J_*DK_];
__device__ float g_bw[H_*S_];
__device__ float g_br[H_*J_];
__device__ float g_attn[H_*S_*S_];     // 201 MB scratch when attn not in d_out
__device__ float g_opre[S_*DM_];
__device__ float g_bmax[2048];
__device__ float g_gmaxf;
__device__ float g_lnf[FEAT_];         // log_norm[f]  (f32, XLA-mimic)
__device__ float g_la[S_];             // log(apos) correctly-rounded f32

// ---------------- XLA-style f32 lgamma (Lanczos g=7), f32 dataflow via double ------
__device__ __forceinline__ float xla_lgammaf(float a) {
    const double C[8] = { 676.520368121885098567009190444019,
                        -1259.13921672240287047156078755283,
                          771.3234287776530788486528258894,
                         -176.61502916214059906584551354,
                           12.507343278686904814458936853,
                           -0.13857109526572011689554707,
                            9.984369578019570859563e-6,
                            1.50563273514931155834e-7 };
    float z = a - 1.0f;                    // exact for our integer-valued conc
    float x = 1.0f;                        // base Lanczos coeff rounds to 1.0f
    #pragma unroll
    for (int k = 0; k < 8; k++) {
        float ck    = (float)C[k];
        float denom = (float)((double)z + (double)(k + 1));
        float term  = (float)((double)ck / (double)denom);
        x = (float)((double)x + (double)term);
    }
    float t     = (float)(7.5 + (double)z);
    float zq    = (float)((double)z / 7.5);
    float l1p   = (float)log1p((double)zq);
    float log_t = (float)((double)((float)2.0149030205422647) + (double)l1p);
    float tol   = (float)((double)t / (double)log_t);
    float zp    = (float)((double)z + 0.5);
    float inner = (float)((double)zp - (double)tol);
    float prod  = (float)((double)inner * (double)log_t);
    float res   = (float)((double)((float)0.91893853320467274178) + (double)prod);
    float lx    = (float)log((double)x);
    return (float)((double)res + (double)lx);
}

// ---------------- pe constants: log_norm[f] and log(apos) tables -------------------
__global__ void pe_const_kernel() {
    int i = blockIdx.x * blockDim.x + threadIdx.x;
    if (i < S_) g_la[i] = (i > 0) ? (float)log((double)i) : 0.0f;
    if (i < FEAT_) {
        float mean = 16.0f * (float)(i + 1);            // linspace(16,2048,128) exact
        float cdiv = mean / 8.0f;                       // exact
        float conc = cdiv * cdiv;                       // exact integers
        float rate = mean / 64.0f;                      // exact
        float lg   = xla_lgammaf(conc);
        float lr   = (float)log((double)rate);
        float t2   = (float)((double)conc * (double)lr);
        g_lnf[i]   = (float)((double)lg - (double)t2);
    }
}

// ---------------- gamma pdf probs (f32 XLA-mimic) + block maxima -------------------
__global__ void pe_prob_kernel() {
    int idx = blockIdx.x * blockDim.x + threadIdx.x;
    float prob = 0.0f;
    if (idx < J_ * FEAT_) {
        int p = idx / FEAT_, f = idx % FEAT_;
        int ap = p - (S_ - 1); if (ap < 0) ap = -ap;
        if (ap > 0) {
            float mean = 16.0f * (float)(f + 1);
            float cdiv = mean / 8.0f;
            float conc = cdiv * cdiv;
            float rate = mean / 64.0f;
            float cm1  = conc - 1.0f;                    // exact
            float apf  = (float)ap;                      // exact
            float lu1  = (float)((double)cm1 * (double)g_la[ap]);
            float lu2  = (float)((double)rate * (double)apf);
            float lu   = (float)((double)lu1 - (double)lu2);
            float arg  = (float)((double)lu - (double)g_lnf[f]);
            prob = (float)exp((double)arg);
        }
        g_pe[p * DM_ + 512 + f] = prob;                  // stash raw prob
    }
    __shared__ float red[256];
    red[threadIdx.x] = prob;
    __syncthreads();
    for (int off = 128; off > 0; off >>= 1) {
        if (threadIdx.x < off) red[threadIdx.x] = fmaxf(red[threadIdx.x], red[threadIdx.x + off]);
        __syncthreads();
    }
    if (threadIdx.x == 0) g_bmax[blockIdx.x] = red[0];
}

__global__ void pe_max_kernel() {
    __shared__ float red[1024];
    int tid = threadIdx.x;
    red[tid] = fmaxf(g_bmax[tid], g_bmax[tid + 1024]);
    __syncthreads();
    for (int off = 512; off > 0; off >>= 1) {
        if (tid < off) red[tid] = fmaxf(red[tid], red[tid + off]);
        __syncthreads();
    }
    if (tid == 0) g_gmaxf = red[0];
}

__global__ void pe_fill_kernel() {
    int idx = blockIdx.x * blockDim.x + threadIdx.x;
    if (idx >= J_ * FEAT_) return;
    int p = idx / FEAT_, f = idx % FEAT_;
    int pos = p - (S_ - 1);
    float apos = (float)(pos < 0 ? -pos : pos);
    float sgn  = (pos > 0) ? 1.0f : (pos < 0 ? -1.0f : 0.0f);
    // half_life = 2^(3 + f*(8/127))  (f32 linspace then pow)
    float step = (float)(8.0 / 127.0);
    float ex   = (float)(3.0 + (double)((float)((double)step * (double)f)));
    float hl   = (float)exp2((double)ex);
    float c    = (float)((double)(-(float)0.6931471805599453) / (double)hl);
    float arg  = (float)((double)c * (double)apos);
    float e1   = (float)exp((double)arg);
    float cw   = exp2f((float)(f + 1)) - 1.0f;           // inf at f=127 matches ref
    float cm   = (cw > apos) ? 1.0f : 0.0f;
    float gam  = (float)((double)g_pe[p * DM_ + 512 + f] / (double)g_gmaxf);
    float* row = g_pe + (size_t)p * DM_;
    row[0   + f] = e1;
    row[128 + f] = e1 * sgn;
    row[256 + f] = cm;
    row[384 + f] = cm * sgn;
    row[512 + f] = gam;
    row[640 + f] = gam * sgn;
}

// ---------------- GEMM: A[M,768] @ W[768,768] -> head layout dst[h][M][64] ---------
// src_sel: 0 -> use A_ext (harness ptr), 1 -> g_pe. dst_sel: 0 g_qh, 1 g_kh, 2 g_vh, 3 g_rk.
__global__ __launch_bounds__(256) void proj_head_kernel(
    const float* __restrict__ A_ext, const float* __restrict__ W,
    int src_sel, int dst_sel, int M, float scale)
{
    const float* A = src_sel ? g_pe : A_ext;
    float* dst = (dst_sel == 0) ? g_qh : (dst_sel == 1) ? g_kh : (dst_sel == 2) ? g_vh : g_rk;
    __shared__ float As[16 * 65];
    __shared__ float Ws[16 * 65];
    int s0 = blockIdx.y * 64, c0 = blockIdx.x * 64;
    int tid = threadIdx.x, tx = tid & 15, ty = tid >> 4;
    float acc[4][4] = {};
    for (int kk = 0; kk < DM_; kk += 16) {
        for (int i = tid; i < 64 * 16; i += 256) {
            int k = i & 15, s = i >> 4;
            As[k * 65 + s] = (s0 + s < M) ? A[(size_t)(s0 + s) * DM_ + kk + k] : 0.0f;
        }
        for (int i = tid; i < 16 * 64; i += 256) {
            int c = i & 63, k = i >> 6;
            Ws[k * 65 + c] = W[(size_t)(kk + k) * DM_ + c0 + c];
        }
        __syncthreads();
        #pragma unroll
        for (int k = 0; k < 16; k++) {
            float av[4], wv[4];
            #pragma unroll
            for (int i = 0; i < 4; i++) av[i] = As[k * 65 + 4 * ty + i];
            #pragma unroll
            for (int j = 0; j < 4; j++) wv[j] = Ws[k * 65 + 4 * tx + j];
            #pragma unroll
            for (int i = 0; i < 4; i++)
                #pragma unroll
                for (int j = 0; j < 4; j++) acc[i][j] += av[i] * wv[j];
        }
        __syncthreads();
    }
    #pragma unroll
    for (int i = 0; i < 4; i++) {
        int s = s0 + 4 * ty + i;
        if (s >= M) continue;
        #pragma unroll
        for (int j = 0; j < 4; j++) {
            int c = c0 + 4 * tx + j;
            int h = c >> 6, d = c & 63;
            dst[((size_t)h * M + s) * DK_ + d] = acc[i][j] * scale;
        }
    }
}

// ---------------- GEMM with bias: g_opre[2048,768] @ W + b -> dst row-major --------
__global__ __launch_bounds__(256) void gemm_bias_kernel(
    const float* __restrict__ W, const float* __restrict__ bias, float* __restrict__ dst)
{
    __shared__ float As[16 * 65];
    __shared__ float Ws[16 * 65];
    int s0 = blockIdx.y * 64, c0 = blockIdx.x * 64;
    int tid = threadIdx.x, tx = tid & 15, ty = tid >> 4;
    float acc[4][4] = {};
    for (int kk = 0; kk < DM_; kk += 16) {
        for (int i = tid; i < 64 * 16; i += 256) {
            int k = i & 15, s = i >> 4;
            As[k * 65 + s] = g_opre[(size_t)(s0 + s) * DM_ + kk + k];
        }
        for (int i = tid; i < 16 * 64; i += 256) {
            int c = i & 63, k = i >> 6;
            Ws[k * 65 + c] = W[(size_t)(kk + k) * DM_ + c0 + c];
        }
        __syncthreads();
        #pragma unroll
        for (int k = 0; k < 16; k++) {
            float av[4], wv[4];
            #pragma unroll
            for (int i = 0; i < 4; i++) av[i] = As[k * 65 + 4 * ty + i];
            #pragma unroll
            for (int j = 0; j < 4; j++) wv[j] = Ws[k * 65 + 4 * tx + j];
            #pragma unroll
            for (int i = 0; i < 4; i++)
                #pragma unroll
                for (int j = 0; j < 4; j++) acc[i][j] += av[i] * wv[j];
        }
        __syncthreads();
    }
    #pragma unroll
    for (int i = 0; i < 4; i++) {
        int s = s0 + 4 * ty + i;
        #pragma unroll
        for (int j = 0; j < 4; j++) {
            int c = c0 + 4 * tx + j;
            dst[(size_t)s * DM_ + c] = acc[i][j] + bias[c];
        }
    }
}

// ---------------- bias vectors: out[h][t] = rvec[h,:] . mat[h][t][:] ---------------
// mat_sel: 0 -> g_kh -> g_bw (M=S), 1 -> g_rk -> g_br (M=J)
__global__ void bias_kernel(const float* __restrict__ rvec, int mat_sel, int M)
{
    int idx = blockIdx.x * blockDim.x + threadIdx.x;
    if (idx >= H_ * M) return;
    const float* mat = mat_sel ? g_rk : g_kh;
    float* out = mat_sel ? g_br : g_bw;
    int h = idx / M, t = idx % M;
    const float* r = rvec + h * DK_;
    const float* m = mat + ((size_t)h * M + t) * DK_;
    float s = 0.0f;
    #pragma unroll
    for (int d = 0; d < DK_; d++) s += r[d] * m[d];
    out[idx] = s;
}

// ---------------- fused logits: content + shifted-rel (static smem, 2 d-phases) ----
// logit[h,s,t] = qh[h,s,:].(kh[h,t,:] + rk[h, t-s+S-1, :]) + bw[h,t] + br[h, t-s+S-1]
__global__ __launch_bounds__(256) void logits_kernel(float* __restrict__ attn_arg)
{
    __shared__ float qs[64 * 33];
    __shared__ float ks[64 * 33];
    __shared__ float rs[32 * 129];
    float* attn = attn_arg ? attn_arg : g_attn;
    int h = blockIdx.z, t0 = blockIdx.x * 64, s0 = blockIdx.y * 64;
    int tid = threadIdx.x, tx = tid & 15, ty = tid >> 4;

    const float* qb = g_qh + ((size_t)h * S_ + s0) * DK_;
    const float* kb = g_kh + ((size_t)h * S_ + t0) * DK_;
    int jbase = t0 - s0 + (S_ - 1) - 63;                 // in [0, 4094-126]
    const float* rb = g_rk + ((size_t)h * J_ + jbase) * DK_;

    float acc[4][4] = {};
    int sB = 4 * ty, tB = 4 * tx;
    int jl0 = tB - sB + 63;

    #pragma unroll
    for (int half = 0; half < 2; half++) {
        int dbase = half * 32;
        __syncthreads();
        for (int i = tid; i < 64 * 32; i += 256) {
            int dl = i & 31, r = i >> 5;
            qs[r * 33 + dl] = qb[(size_t)r * DK_ + dbase + dl];
            ks[r * 33 + dl] = kb[(size_t)r * DK_ + dbase + dl];
        }
        for (int i = tid; i < 127 * 32; i += 256) {
            int dl = i & 31, jl = i >> 5;
            rs[dl * 129 + jl] = rb[(size_t)jl * DK_ + dbase + dl];
        }
        __syncthreads();

        #pragma unroll 8
        for (int dl = 0; dl < 32; dl++) {
            float qv[4], kv[4], rv[7];
            #pragma unroll
            for (int i = 0; i < 4; i++) qv[i] = qs[(sB + i) * 33 + dl];
            #pragma unroll
            for (int j = 0; j < 4; j++) kv[j] = ks[(tB + j) * 33 + dl];
            #pragma unroll
            for (int m = 0; m < 7; m++) rv[m] = rs[dl * 129 + jl0 + m - 3];
            #pragma unroll
            for (int i = 0; i < 4; i++)
                #pragma unroll
                for (int j = 0; j < 4; j++)
                    acc[i][j] += qv[i] * (kv[j] + rv[j - i + 3]);
        }
    }

    #pragma unroll
    for (int i = 0; i < 4; i++) {
        int s = s0 + sB + i;
        #pragma unroll
        for (int j = 0; j < 4; j++) {
            int t = t0 + tB + j;
            int jg = t - s + (S_ - 1);
            attn[((size_t)h * S_ + s) * S_ + t] = acc[i][j] + g_bw[h * S_ + t] + g_br[h * J_ + jg];
        }
    }
}

// ---------------- row softmax in place -------------------------------------------
__global__ __launch_bounds__(256) void softmax_kernel(float* __restrict__ attn_arg)
{
    float* attn = attn_arg ? attn_arg : g_attn;
    size_t row = blockIdx.x;
    float* x = attn + row * S_;
    int tid = threadIdx.x;
    float v[8];
    float m = -1e30f;
    #pragma unroll
    for (int i = 0; i < 8; i++) { v[i] = x[tid + 256 * i]; m = fmaxf(m, v[i]); }
    __shared__ float red[256];
    red[tid] = m; __syncthreads();
    for (int off = 128; off > 0; off >>= 1) {
        if (tid < off) red[tid] = fmaxf(red[tid], red[tid + off]);
        __syncthreads();
    }
    m = red[0]; __syncthreads();
    float sum = 0.0f;
    #pragma unroll
    for (int i = 0; i < 8; i++) { v[i] = expf(v[i] - m); sum += v[i]; }
    red[tid] = sum; __syncthreads();
    for (int off = 128; off > 0; off >>= 1) {
        if (tid < off) red[tid] += red[tid + off];
        __syncthreads();
    }
    float inv = 1.0f / red[0];
    #pragma unroll
    for (int i = 0; i < 8; i++) x[tid + 256 * i] = v[i] * inv;
}

// ---------------- attn @ V -> merged g_opre[s][768] --------------------------------
__global__ __launch_bounds__(256) void av_kernel(const float* __restrict__ attn_arg)
{
    const float* attn = attn_arg ? attn_arg : (const float*)g_attn;
    __shared__ float As[16 * 65];
    __shared__ float Vs[16 * 65];
    int s0 = blockIdx.x * 64, h = blockIdx.y;
    int tid = threadIdx.x, tx = tid & 15, ty = tid >> 4;
    const float* ab = attn + ((size_t)h * S_ + s0) * S_;
    const float* vb = g_vh + (size_t)h * S_ * DK_;
    float acc[4][4] = {};
    for (int kk = 0; kk < S_; kk += 16) {
        for (int i = tid; i < 64 * 16; i += 256) {
            int k = i & 15, s = i >> 4;
            As[k * 65 + s] = ab[(size_t)s * S_ + kk + k];
        }
        for (int i = tid; i < 16 * 64; i += 256) {
            int d = i & 63, k = i >> 6;
            Vs[k * 65 + d] = vb[(size_t)(kk + k) * DK_ + d];
        }
        __syncthreads();
        #pragma unroll
        for (int k = 0; k < 16; k++) {
            float av[4], vv[4];
            #pragma unroll
            for (int i = 0; i < 4; i++) av[i] = As[k * 65 + 4 * ty + i];
            #pragma unroll
            for (int j = 0; j < 4; j++) vv[j] = Vs[k * 65 + 4 * tx + j];
            #pragma unroll
            for (int i = 0; i < 4; i++)
                #pragma unroll
                for (int j = 0; j < 4; j++) acc[i][j] += av[i] * vv[j];
        }
        __syncthreads();
    }
    #pragma unroll
    for (int i = 0; i < 4; i++) {
        int s = s0 + 4 * ty + i;
        #pragma unroll
        for (int j = 0; j < 4; j++)
            g_opre[(size_t)s * DM_ + h * DK_ + 4 * tx + j] = acc[i][j];
    }
}

// ---------------- host launcher: ONLY harness pointers / scalars as kernel args ----
extern "C" void kernel_launch(void* const* d_in, const int* in_sizes, int n_in,
                              void* d_out, int out_size)
{
    const int QKV = 1572864, WMAT = 589824, VEC = 768;
    const float *q, *k, *v, *wq, *wk, *wv, *w_rk, *r_w, *r_r, *w_out, *b_out;
    if (n_in >= 11 && in_sizes[0] == VEC && in_sizes[1] == QKV && in_sizes[5] == QKV
        && in_sizes[6] == WMAT) {
        // alphabetical: b_out,k,q,r_r,r_w,v,w_out,w_rk,wk,wq,wv
        b_out = (const float*)d_in[0];
        k     = (const float*)d_in[1];
        q     = (const float*)d_in[2];
        r_r   = (const float*)d_in[3];
        r_w   = (const float*)d_in[4];
        v     = (const float*)d_in[5];
        w_out = (const float*)d_in[6];
        w_rk  = (const float*)d_in[7];
        wk    = (const float*)d_in[8];
        wq    = (const float*)d_in[9];
        wv    = (const float*)d_in[10];
    } else {
        // reference signature order
        q     = (const float*)d_in[0];
        k     = (const float*)d_in[1];
        v     = (const float*)d_in[2];
        wq    = (const float*)d_in[3];
        wk    = (const float*)d_in[4];
        wv    = (const float*)d_in[5];
        w_rk  = (const float*)d_in[6];
        r_w   = (const float*)d_in[7];
        r_r   = (const float*)d_in[8];
        w_out = (const float*)d_in[9];
        b_out = (const float*)d_in[10];
    }

    const long long OUT_E  = (long long)S_ * DM_;        // 1,572,864
    const long long ATTN_E = (long long)H_ * S_ * S_;    // 50,331,648
    long long os = (long long)out_size;

    float* out_ptr  = (float*)d_out;
    float* attn_ptr = nullptr;     // nullptr -> kernels use internal g_attn scratch
    bool need_out = true;

    if (os >= OUT_E + ATTN_E) {
        attn_ptr = (float*)d_out + OUT_E;                // [out][attn] concatenated
    } else if (os == ATTN_E) {
        attn_ptr = (float*)d_out;                        // attn only
        need_out = false;
    }                                                    // else: out only, attn scratch

    // positional features (f32 XLA-mimic gamma basis; deterministic two-stage max)
    pe_const_kernel<<<8, 256>>>();
    pe_prob_kernel<<<2048, 256>>>();
    pe_max_kernel<<<1, 1024>>>();
    pe_fill_kernel<<<2048, 256>>>();

    // projections into head layout (dst selected device-side)
    proj_head_kernel<<<dim3(12, 32), 256>>>(q, wq, 0, 0, S_, 0.125f);
    proj_head_kernel<<<dim3(12, 32), 256>>>(k, wk, 0, 1, S_, 1.0f);
    proj_head_kernel<<<dim3(12, 32), 256>>>(v, wv, 0, 2, S_, 1.0f);
    proj_head_kernel<<<dim3(12, 64), 256>>>(nullptr, w_rk, 1, 3, J_, 1.0f);

    // per-t / per-j bias vectors (r_w . kh -> g_bw, r_r . rk -> g_br)
    bias_kernel<<<(H_ * S_ + 255) / 256, 256>>>(r_w, 0, S_);
    bias_kernel<<<(H_ * J_ + 255) / 256, 256>>>(r_r, 1, J_);

    // fused content+rel logits (relative_shift folded into indexing)
    logits_kernel<<<dim3(32, 32, 12), 256>>>(attn_ptr);

    // softmax in place
    softmax_kernel<<<H_ * S_, 256>>>(attn_ptr);

    if (need_out) {
        av_kernel<<<dim3(32, 12), 256>>>(attn_ptr);
        gemm_bias_kernel<<<dim3(12, 32), 256>>>(w_out, b_out, out_ptr);
    }
}

// round 5
// speedup vs baseline: 1.7943x; 1.7943x over previous
#include <cuda_runtime.h>
#include <math.h>

#define S_    2048
#define DM_   768
#define H_    12
#define DK_   64
#define FEAT_ 128
#define J_    4095   /* 2S-1 */

typedef unsigned long long u64;

__device__ __forceinline__ u64 pack2(float lo, float hi) {
    u64 r; asm("mov.b64 %0, {%1, %2};" : "=l"(r) : "f"(lo), "f"(hi)); return r;
}
__device__ __forceinline__ void unpack2(u64 v, float& lo, float& hi) {
    asm("mov.b64 {%0, %1}, %2;" : "=f"(lo), "=f"(hi) : "l"(v));
}
__device__ __forceinline__ void fma2(u64& d, u64 a, u64 b) {
    asm("fma.rn.f32x2 %0, %1, %2, %0;" : "+l"(d) : "l"(a), "l"(b));
}

// ---------------- scratch (static device globals; referenced ONLY in device code) --
__device__ float g_qh[H_*S_*DK_];
__device__ float g_kh[H_*S_*DK_];
__device__ float g_vh[H_*S_*DK_];
__device__ float g_pe[J_*DM_];
__device__ float g_rk[H_*J_*DK_];
__device__ float g_bw[H_*S_];
__device__ float g_br[H_*J_];
__device__ float g_attn[H_*S_*S_];
__device__ float g_opre[S_*DM_];
__device__ float g_bmax[2048];
__device__ float g_gmaxf;
__device__ float g_lnf[FEAT_];
__device__ float g_la[S_];

// ---------------- XLA-style f32 lgamma (Lanczos g=7), f32 dataflow via double ------
__device__ __forceinline__ float xla_lgammaf(float a) {
    const double C[8] = { 676.520368121885098567009190444019,
                        -1259.13921672240287047156078755283,
                          771.3234287776530788486528258894,
                         -176.61502916214059906584551354,
                           12.507343278686904814458936853,
                           -0.13857109526572011689554707,
                            9.984369578019570859563e-6,
                            1.50563273514931155834e-7 };
    float z = a - 1.0f;
    float x = 1.0f;
    #pragma unroll
    for (int k = 0; k < 8; k++) {
        float ck    = (float)C[k];
        float denom = (float)((double)z + (double)(k + 1));
        float term  = (float)((double)ck / (double)denom);
        x = (float)((double)x + (double)term);
    }
    float t     = (float)(7.5 + (double)z);
    float zq    = (float)((double)z / 7.5);
    float l1p   = (float)log1p((double)zq);
    float log_t = (float)((double)((float)2.0149030205422647) + (double)l1p);
    float tol   = (float)((double)t / (double)log_t);
    float zp    = (float)((double)z + 0.5);
    float inner = (float)((double)zp - (double)tol);
    float prod  = (float)((double)inner * (double)log_t);
    float res   = (float)((double)((float)0.91893853320467274178) + (double)prod);
    float lx    = (float)log((double)x);
    return (float)((double)res + (double)lx);
}

__global__ void pe_const_kernel() {
    int i = blockIdx.x * blockDim.x + threadIdx.x;
    if (i < S_) g_la[i] = (i > 0) ? (float)log((double)i) : 0.0f;
    if (i < FEAT_) {
        float mean = 16.0f * (float)(i + 1);
        float cdiv = mean / 8.0f;
        float conc = cdiv * cdiv;
        float rate = mean / 64.0f;
        float lg   = xla_lgammaf(conc);
        float lr   = (float)log((double)rate);
        float t2   = (float)((double)conc * (double)lr);
        g_lnf[i]   = (float)((double)lg - (double)t2);
    }
}

__global__ void pe_prob_kernel() {
    int idx = blockIdx.x * blockDim.x + threadIdx.x;
    float prob = 0.0f;
    if (idx < J_ * FEAT_) {
        int p = idx / FEAT_, f = idx % FEAT_;
        int ap = p - (S_ - 1); if (ap < 0) ap = -ap;
        if (ap > 0) {
            float mean = 16.0f * (float)(f + 1);
            float cdiv = mean / 8.0f;
            float conc = cdiv * cdiv;
            float rate = mean / 64.0f;
            float cm1  = conc - 1.0f;
            float apf  = (float)ap;
            float lu1  = (float)((double)cm1 * (double)g_la[ap]);
            float lu2  = (float)((double)rate * (double)apf);
            float lu   = (float)((double)lu1 - (double)lu2);
            float arg  = (float)((double)lu - (double)g_lnf[f]);
            prob = (float)exp((double)arg);
        }
        g_pe[p * DM_ + 512 + f] = prob;
    }
    __shared__ float red[256];
    red[threadIdx.x] = prob;
    __syncthreads();
    for (int off = 128; off > 0; off >>= 1) {
        if (threadIdx.x < off) red[threadIdx.x] = fmaxf(red[threadIdx.x], red[threadIdx.x + off]);
        __syncthreads();
    }
    if (threadIdx.x == 0) g_bmax[blockIdx.x] = red[0];
}

__global__ void pe_max_kernel() {
    __shared__ float red[1024];
    int tid = threadIdx.x;
    red[tid] = fmaxf(g_bmax[tid], g_bmax[tid + 1024]);
    __syncthreads();
    for (int off = 512; off > 0; off >>= 1) {
        if (tid < off) red[tid] = fmaxf(red[tid], red[tid + off]);
        __syncthreads();
    }
    if (tid == 0) g_gmaxf = red[0];
}

__global__ void pe_fill_kernel() {
    int idx = blockIdx.x * blockDim.x + threadIdx.x;
    if (idx >= J_ * FEAT_) return;
    int p = idx / FEAT_, f = idx % FEAT_;
    int pos = p - (S_ - 1);
    float apos = (float)(pos < 0 ? -pos : pos);
    float sgn  = (pos > 0) ? 1.0f : (pos < 0 ? -1.0f : 0.0f);
    float step = (float)(8.0 / 127.0);
    float ex   = (float)(3.0 + (double)((float)((double)step * (double)f)));
    float hl   = (float)exp2((double)ex);
    float c    = (float)((double)(-(float)0.6931471805599453) / (double)hl);
    float arg  = (float)((double)c * (double)apos);
    float e1   = (float)exp((double)arg);
    float cw   = exp2f((float)(f + 1)) - 1.0f;
    float cm   = (cw > apos) ? 1.0f : 0.0f;
    float gam  = (float)((double)g_pe[p * DM_ + 512 + f] / (double)g_gmaxf);
    float* row = g_pe + (size_t)p * DM_;
    row[0   + f] = e1;
    row[128 + f] = e1 * sgn;
    row[256 + f] = cm;
    row[384 + f] = cm * sgn;
    row[512 + f] = gam;
    row[640 + f] = gam * sgn;
}

// ======== projection GEMM: A[M,768] @ W[768,768] -> head layout dst[h][M][64] ======
// tile 128 rows x 64 cols, 128 threads, 8x8 per thread, f32x2 FMA.
// src_sel: 0 -> A_ext, 1 -> g_pe.  dst_sel: 0 g_qh, 1 g_kh, 2 g_vh, 3 g_rk.
__global__ __launch_bounds__(128) void proj_head_kernel(
    const float* __restrict__ A_ext, const float* __restrict__ W,
    int src_sel, int dst_sel, int M, float scale)
{
    const float* A = src_sel ? g_pe : A_ext;
    float* dst = (dst_sel == 0) ? g_qh : (dst_sel == 1) ? g_kh : (dst_sel == 2) ? g_vh : g_rk;
    __shared__ float AsT[16 * 132];
    __shared__ float Ws[16 * 68];
    int r0 = blockIdx.y * 128, c0 = blockIdx.x * 64;
    int h  = c0 >> 6;
    int tid = threadIdx.x, tx = tid & 7, ty = tid >> 3;
    u64 acc[8][4];
    #pragma unroll
    for (int i = 0; i < 8; i++)
        #pragma unroll
        for (int j = 0; j < 4; j++) acc[i][j] = 0ull;

    int vo = 8 * tx + ((tx >= 4) ? 4 : 0);

    for (int kk = 0; kk < DM_; kk += 16) {
        __syncthreads();
        // A tile transpose-load: 128 rows x 16 k
        #pragma unroll
        for (int it = 0; it < 4; it++) {
            int lin = tid + it * 128;          // < 512
            int r = lin >> 2, c4 = lin & 3;
            float4 val = make_float4(0.f, 0.f, 0.f, 0.f);
            if (r0 + r < M)
                val = *(const float4*)(A + (size_t)(r0 + r) * DM_ + kk + 4 * c4);
            AsT[(4 * c4 + 0) * 132 + r] = val.x;
            AsT[(4 * c4 + 1) * 132 + r] = val.y;
            AsT[(4 * c4 + 2) * 132 + r] = val.z;
            AsT[(4 * c4 + 3) * 132 + r] = val.w;
        }
        // W tile: 16 k x 64 c with +4 gap after col 32
        #pragma unroll
        for (int it = 0; it < 2; it++) {
            int lin = tid + it * 128;          // < 256
            int kx = lin >> 4, c4 = lin & 15;
            float4 val = *(const float4*)(W + (size_t)(kk + kx) * DM_ + c0 + 4 * c4);
            int dd = 4 * c4 + ((c4 >= 8) ? 4 : 0);
            *(float4*)(Ws + kx * 68 + dd) = val;
        }
        __syncthreads();

        #pragma unroll 4
        for (int kx = 0; kx < 16; kx++) {
            float4 aa = *(const float4*)(AsT + kx * 132 + 8 * ty);
            float4 ab = *(const float4*)(AsT + kx * 132 + 8 * ty + 4);
            float4 wa = *(const float4*)(Ws + kx * 68 + vo);
            float4 wb = *(const float4*)(Ws + kx * 68 + vo + 4);
            u64 ap[8] = { pack2(aa.x, aa.x), pack2(aa.y, aa.y), pack2(aa.z, aa.z), pack2(aa.w, aa.w),
                          pack2(ab.x, ab.x), pack2(ab.y, ab.y), pack2(ab.z, ab.z), pack2(ab.w, ab.w) };
            u64 wp[4] = { pack2(wa.x, wa.y), pack2(wa.z, wa.w), pack2(wb.x, wb.y), pack2(wb.z, wb.w) };
            #pragma unroll
            for (int i = 0; i < 8; i++)
                #pragma unroll
                for (int j = 0; j < 4; j++) fma2(acc[i][j], ap[i], wp[j]);
        }
    }

    #pragma unroll
    for (int i = 0; i < 8; i++) {
        int r = r0 + 8 * ty + i;
        if (r >= M) continue;
        float ov[8];
        #pragma unroll
        for (int j = 0; j < 4; j++) unpack2(acc[i][j], ov[2 * j], ov[2 * j + 1]);
        float4 o0 = make_float4(ov[0] * scale, ov[1] * scale, ov[2] * scale, ov[3] * scale);
        float4 o1 = make_float4(ov[4] * scale, ov[5] * scale, ov[6] * scale, ov[7] * scale);
        float* dp = dst + ((size_t)h * M + r) * DK_ + 8 * tx;
        *(float4*)dp = o0;
        *(float4*)(dp + 4) = o1;
    }
}

// ======== output GEMM: g_opre[2048,768] @ W + bias -> dst row-major ================
__global__ __launch_bounds__(128) void gemm_bias_kernel(
    const float* __restrict__ W, const float* __restrict__ bias, float* __restrict__ dst)
{
    __shared__ float AsT[16 * 132];
    __shared__ float Ws[16 * 68];
    int r0 = blockIdx.y * 128, c0 = blockIdx.x * 64;
    int tid = threadIdx.x, tx = tid & 7, ty = tid >> 3;
    u64 acc[8][4];
    #pragma unroll
    for (int i = 0; i < 8; i++)
        #pragma unroll
        for (int j = 0; j < 4; j++) acc[i][j] = 0ull;
    int vo = 8 * tx + ((tx >= 4) ? 4 : 0);

    for (int kk = 0; kk < DM_; kk += 16) {
        __syncthreads();
        #pragma unroll
        for (int it = 0; it < 4; it++) {
            int lin = tid + it * 128;
            int r = lin >> 2, c4 = lin & 3;
            float4 val = *(const float4*)(g_opre + (size_t)(r0 + r) * DM_ + kk + 4 * c4);
            AsT[(4 * c4 + 0) * 132 + r] = val.x;
            AsT[(4 * c4 + 1) * 132 + r] = val.y;
            AsT[(4 * c4 + 2) * 132 + r] = val.z;
            AsT[(4 * c4 + 3) * 132 + r] = val.w;
        }
        #pragma unroll
        for (int it = 0; it < 2; it++) {
            int lin = tid + it * 128;
            int kx = lin >> 4, c4 = lin & 15;
            float4 val = *(const float4*)(W + (size_t)(kk + kx) * DM_ + c0 + 4 * c4);
            int dd = 4 * c4 + ((c4 >= 8) ? 4 : 0);
            *(float4*)(Ws + kx * 68 + dd) = val;
        }
        __syncthreads();

        #pragma unroll 4
        for (int kx = 0; kx < 16; kx++) {
            float4 aa = *(const float4*)(AsT + kx * 132 + 8 * ty);
            float4 ab = *(const float4*)(AsT + kx * 132 + 8 * ty + 4);
            float4 wa = *(const float4*)(Ws + kx * 68 + vo);
            float4 wb = *(const float4*)(Ws + kx * 68 + vo + 4);
            u64 ap[8] = { pack2(aa.x, aa.x), pack2(aa.y, aa.y), pack2(aa.z, aa.z), pack2(aa.w, aa.w),
                          pack2(ab.x, ab.x), pack2(ab.y, ab.y), pack2(ab.z, ab.z), pack2(ab.w, ab.w) };
            u64 wp[4] = { pack2(wa.x, wa.y), pack2(wa.z, wa.w), pack2(wb.x, wb.y), pack2(wb.z, wb.w) };
            #pragma unroll
            for (int i = 0; i < 8; i++)
                #pragma unroll
                for (int j = 0; j < 4; j++) fma2(acc[i][j], ap[i], wp[j]);
        }
    }

    float4 b0 = *(const float4*)(bias + c0 + 8 * tx);
    float4 b1 = *(const float4*)(bias + c0 + 8 * tx + 4);
    #pragma unroll
    for (int i = 0; i < 8; i++) {
        int r = r0 + 8 * ty + i;
        float ov[8];
        #pragma unroll
        for (int j = 0; j < 4; j++) unpack2(acc[i][j], ov[2 * j], ov[2 * j + 1]);
        float4 o0 = make_float4(ov[0] + b0.x, ov[1] + b0.y, ov[2] + b0.z, ov[3] + b0.w);
        float4 o1 = make_float4(ov[4] + b1.x, ov[5] + b1.y, ov[6] + b1.z, ov[7] + b1.w);
        float* dp = dst + (size_t)r * DM_ + c0 + 8 * tx;
        *(float4*)dp = o0;
        *(float4*)(dp + 4) = o1;
    }
}

// ---------------- bias vectors: out[h][t] = rvec[h,:] . mat[h][t][:] ---------------
__global__ void bias_kernel(const float* __restrict__ rvec, int mat_sel, int M)
{
    int idx = blockIdx.x * blockDim.x + threadIdx.x;
    if (idx >= H_ * M) return;
    const float* mat = mat_sel ? g_rk : g_kh;
    float* out = mat_sel ? g_br : g_bw;
    int h = idx / M, t = idx % M;
    const float* r = rvec + h * DK_;
    const float* m = mat + ((size_t)h * M + t) * DK_;
    float s = 0.0f;
    #pragma unroll
    for (int d = 0; d < DK_; d++) s += r[d] * m[d];
    out[idx] = s;
}

// ======== fused logits: content + shifted-rel, 128x128 tile, 8x8/thread, f32x2 =====
// logit[h,s,t] = qh[h,s,:].kh[h,t,:] + qh[h,s,:].rk[h,t-s+2047,:] + bw[h,t] + br[h,t-s+2047]
__global__ __launch_bounds__(256) void logits_kernel(float* __restrict__ attn_arg)
{
    __shared__ float qsT[16 * 132];   // [d-local][s]
    __shared__ float ksT[16 * 132];   // [d-local][t]
    __shared__ float rs [16 * 256];   // [d-local][j-local], window of 255
    __shared__ float bwS[128];
    __shared__ float brS[256];
    float* attn = attn_arg ? attn_arg : g_attn;
    int h = blockIdx.z, t0 = blockIdx.x * 128, s0 = blockIdx.y * 128;
    int tid = threadIdx.x, tx = tid & 15, ty = tid >> 4;

    const float* qb = g_qh + ((size_t)h * S_ + s0) * DK_;
    const float* kb = g_kh + ((size_t)h * S_ + t0) * DK_;
    int jbase = t0 - s0 + 1920;                    // in [0, 3840]
    const float* rb = g_rk + ((size_t)h * J_ + jbase) * DK_;

    if (tid < 128) bwS[tid] = g_bw[h * S_ + t0 + tid];
    if (tid < 255) brS[tid] = g_br[h * J_ + jbase + tid];

    u64 acc[8][4];
    #pragma unroll
    for (int i = 0; i < 8; i++)
        #pragma unroll
        for (int j = 0; j < 4; j++) acc[i][j] = 0ull;

    int rb0 = 8 * (tx - ty) + 120;                 // 32B-aligned window base

    for (int phase = 0; phase < 4; phase++) {
        int dbase = phase * 16;
        __syncthreads();
        // q,k tiles: 128 rows x 16 d each, transposed
        #pragma unroll
        for (int it = 0; it < 4; it++) {
            int lin = tid + it * 256;              // < 1024
            int m = lin >> 9;                      // 0: q, 1: k
            int l2 = lin & 511;
            int r = l2 >> 2, c4 = l2 & 3;
            const float* src = (m ? kb : qb) + (size_t)r * DK_ + dbase + 4 * c4;
            float4 val = *(const float4*)src;
            float* dstm = m ? ksT : qsT;
            dstm[(4 * c4 + 0) * 132 + r] = val.x;
            dstm[(4 * c4 + 1) * 132 + r] = val.y;
            dstm[(4 * c4 + 2) * 132 + r] = val.z;
            dstm[(4 * c4 + 3) * 132 + r] = val.w;
        }
        // r window: 255 rows x 16 d, transposed
        #pragma unroll
        for (int it = 0; it < 4; it++) {
            int lin = tid + it * 256;              // < 1020
            if (lin < 1020) {
                int jl = lin >> 2, c4 = lin & 3;
                float4 val = *(const float4*)(rb + (size_t)jl * DK_ + dbase + 4 * c4);
                rs[(4 * c4 + 0) * 256 + jl] = val.x;
                rs[(4 * c4 + 1) * 256 + jl] = val.y;
                rs[(4 * c4 + 2) * 256 + jl] = val.z;
                rs[(4 * c4 + 3) * 256 + jl] = val.w;
            }
        }
        __syncthreads();

        #pragma unroll 2
        for (int dl = 0; dl < 16; dl++) {
            float4 qa = *(const float4*)(qsT + dl * 132 + 8 * ty);
            float4 qb4 = *(const float4*)(qsT + dl * 132 + 8 * ty + 4);
            float4 ka = *(const float4*)(ksT + dl * 132 + 8 * tx);
            float4 kb4 = *(const float4*)(ksT + dl * 132 + 8 * tx + 4);
            const float* rp = rs + dl * 256 + rb0;
            float4 r0 = *(const float4*)(rp);
            float4 r1 = *(const float4*)(rp + 4);
            float4 r2 = *(const float4*)(rp + 8);
            float4 r3 = *(const float4*)(rp + 12);
            float rw[16] = { r0.x, r0.y, r0.z, r0.w, r1.x, r1.y, r1.z, r1.w,
                             r2.x, r2.y, r2.z, r2.w, r3.x, r3.y, r3.z, r3.w };
            u64 qq[8] = { pack2(qa.x, qa.x), pack2(qa.y, qa.y), pack2(qa.z, qa.z), pack2(qa.w, qa.w),
                          pack2(qb4.x, qb4.x), pack2(qb4.y, qb4.y), pack2(qb4.z, qb4.z), pack2(qb4.w, qb4.w) };
            u64 kp[4] = { pack2(ka.x, ka.y), pack2(ka.z, ka.w), pack2(kb4.x, kb4.y), pack2(kb4.z, kb4.w) };
            u64 E[7], O[7];
            #pragma unroll
            for (int v = 0; v < 7; v++) {
                E[v] = pack2(rw[2 * v], rw[2 * v + 1]);
                O[v] = pack2(rw[2 * v + 1], rw[2 * v + 2]);
            }
            #pragma unroll
            for (int i = 0; i < 8; i++) {
                int eb = (7 - i) >> 1;
                #pragma unroll
                for (int j = 0; j < 4; j++) {
                    fma2(acc[i][j], qq[i], kp[j]);
                    fma2(acc[i][j], qq[i], (i & 1) ? E[j + eb] : O[j + eb]);
                }
            }
        }
    }

    #pragma unroll
    for (int i = 0; i < 8; i++) {
        int s_loc = 8 * ty + i;
        int s = s0 + s_loc;
        float ov[8];
        #pragma unroll
        for (int j = 0; j < 4; j++) unpack2(acc[i][j], ov[2 * j], ov[2 * j + 1]);
        #pragma unroll
        for (int jj = 0; jj < 8; jj++) {
            int tl = 8 * tx + jj;
            ov[jj] += bwS[tl] + brS[tl - s_loc + 127];
        }
        float* dp = attn + ((size_t)h * S_ + s) * S_ + t0 + 8 * tx;
        *(float4*)dp       = make_float4(ov[0], ov[1], ov[2], ov[3]);
        *(float4*)(dp + 4) = make_float4(ov[4], ov[5], ov[6], ov[7]);
    }
}

// ---------------- row softmax in place -------------------------------------------
__global__ __launch_bounds__(256) void softmax_kernel(float* __restrict__ attn_arg)
{
    float* attn = attn_arg ? attn_arg : g_attn;
    size_t row = blockIdx.x;
    float* x = attn + row * S_;
    int tid = threadIdx.x;
    float v[8];
    float m = -1e30f;
    #pragma unroll
    for (int i = 0; i < 8; i++) { v[i] = x[tid + 256 * i]; m = fmaxf(m, v[i]); }
    __shared__ float red[256];
    red[tid] = m; __syncthreads();
    for (int off = 128; off > 0; off >>= 1) {
        if (tid < off) red[tid] = fmaxf(red[tid], red[tid + off]);
        __syncthreads();
    }
    m = red[0]; __syncthreads();
    float sum = 0.0f;
    #pragma unroll
    for (int i = 0; i < 8; i++) { v[i] = expf(v[i] - m); sum += v[i]; }
    red[tid] = sum; __syncthreads();
    for (int off = 128; off > 0; off >>= 1) {
        if (tid < off) red[tid] += red[tid + off];
        __syncthreads();
    }
    float inv = 1.0f / red[0];
    #pragma unroll
    for (int i = 0; i < 8; i++) x[tid + 256 * i] = v[i] * inv;
}

// ======== attn @ V -> g_opre[s][768]: tile 128s x 64d, 128 thr, 8x8, f32x2 =========
__global__ __launch_bounds__(128) void av_kernel(const float* __restrict__ attn_arg)
{
    const float* attn = attn_arg ? attn_arg : (const float*)g_attn;
    __shared__ float AsT[16 * 132];
    __shared__ float Vs[16 * 68];
    int s0 = blockIdx.x * 128, h = blockIdx.y;
    int tid = threadIdx.x, tx = tid & 7, ty = tid >> 3;
    const float* ab = attn + ((size_t)h * S_ + s0) * S_;
    const float* vb = g_vh + (size_t)h * S_ * DK_;
    u64 acc[8][4];
    #pragma unroll
    for (int i = 0; i < 8; i++)
        #pragma unroll
        for (int j = 0; j < 4; j++) acc[i][j] = 0ull;
    int vo = 8 * tx + ((tx >= 4) ? 4 : 0);

    for (int kk = 0; kk < S_; kk += 16) {
        __syncthreads();
        #pragma unroll
        for (int it = 0; it < 4; it++) {
            int lin = tid + it * 128;              // < 512
            int s = lin >> 2, c4 = lin & 3;
            float4 val = *(const float4*)(ab + (size_t)s * S_ + kk + 4 * c4);
            AsT[(4 * c4 + 0) * 132 + s] = val.x;
            AsT[(4 * c4 + 1) * 132 + s] = val.y;
            AsT[(4 * c4 + 2) * 132 + s] = val.z;
            AsT[(4 * c4 + 3) * 132 + s] = val.w;
        }
        #pragma unroll
        for (int it = 0; it < 2; it++) {
            int lin = tid + it * 128;              // < 256
            int kx = lin >> 4, c4 = lin & 15;
            float4 val = *(const float4*)(vb + (size_t)(kk + kx) * DK_ + 4 * c4);
            int dd = 4 * c4 + ((c4 >= 8) ? 4 : 0);
            *(float4*)(Vs + kx * 68 + dd) = val;
        }
        __syncthreads();

        #pragma unroll 4
        for (int kx = 0; kx < 16; kx++) {
            float4 aa = *(const float4*)(AsT + kx * 132 + 8 * ty);
            float4 ab4 = *(const float4*)(AsT + kx * 132 + 8 * ty + 4);
            float4 va = *(const float4*)(Vs + kx * 68 + vo);
            float4 vb4 = *(const float4*)(Vs + kx * 68 + vo + 4);
            u64 ap[8] = { pack2(aa.x, aa.x), pack2(aa.y, aa.y), pack2(aa.z, aa.z), pack2(aa.w, aa.w),
                          pack2(ab4.x, ab4.x), pack2(ab4.y, ab4.y), pack2(ab4.z, ab4.z), pack2(ab4.w, ab4.w) };
            u64 vp[4] = { pack2(va.x, va.y), pack2(va.z, va.w), pack2(vb4.x, vb4.y), pack2(vb4.z, vb4.w) };
            #pragma unroll
            for (int i = 0; i < 8; i++)
                #pragma unroll
                for (int j = 0; j < 4; j++) fma2(acc[i][j], ap[i], vp[j]);
        }
    }

    #pragma unroll
    for (int i = 0; i < 8; i++) {
        int s = s0 + 8 * ty + i;
        float ov[8];
        #pragma unroll
        for (int j = 0; j < 4; j++) unpack2(acc[i][j], ov[2 * j], ov[2 * j + 1]);
        float* dp = g_opre + (size_t)s * DM_ + h * DK_ + 8 * tx;
        *(float4*)dp       = make_float4(ov[0], ov[1], ov[2], ov[3]);
        *(float4*)(dp + 4) = make_float4(ov[4], ov[5], ov[6], ov[7]);
    }
}

// ---------------- host launcher (kernel launches ONLY; no device symbols as args) --
extern "C" void kernel_launch(void* const* d_in, const int* in_sizes, int n_in,
                              void* d_out, int out_size)
{
    const int QKV = 1572864, WMAT = 589824, VEC = 768;
    const float *q, *k, *v, *wq, *wk, *wv, *w_rk, *r_w, *r_r, *w_out, *b_out;
    if (n_in >= 11 && in_sizes[0] == VEC && in_sizes[1] == QKV && in_sizes[5] == QKV
        && in_sizes[6] == WMAT) {
        b_out = (const float*)d_in[0];
        k     = (const float*)d_in[1];
        q     = (const float*)d_in[2];
        r_r   = (const float*)d_in[3];
        r_w   = (const float*)d_in[4];
        v     = (const float*)d_in[5];
        w_out = (const float*)d_in[6];
        w_rk  = (const float*)d_in[7];
        wk    = (const float*)d_in[8];
        wq    = (const float*)d_in[9];
        wv    = (const float*)d_in[10];
    } else {
        q     = (const float*)d_in[0];
        k     = (const float*)d_in[1];
        v     = (const float*)d_in[2];
        wq    = (const float*)d_in[3];
        wk    = (const float*)d_in[4];
        wv    = (const float*)d_in[5];
        w_rk  = (const float*)d_in[6];
        r_w   = (const float*)d_in[7];
        r_r   = (const float*)d_in[8];
        w_out = (const float*)d_in[9];
        b_out = (const float*)d_in[10];
    }

    const long long OUT_E  = (long long)S_ * DM_;
    const long long ATTN_E = (long long)H_ * S_ * S_;
    long long os = (long long)out_size;

    float* out_ptr  = (float*)d_out;
    float* attn_ptr = nullptr;
    bool need_out = true;

    if (os >= OUT_E + ATTN_E) {
        attn_ptr = (float*)d_out + OUT_E;
    } else if (os == ATTN_E) {
        attn_ptr = (float*)d_out;
        need_out = false;
    }

    pe_const_kernel<<<8, 256>>>();
    pe_prob_kernel<<<2048, 256>>>();
    pe_max_kernel<<<1, 1024>>>();
    pe_fill_kernel<<<2048, 256>>>();

    proj_head_kernel<<<dim3(12, 16), 128>>>(q, wq, 0, 0, S_, 0.125f);
    proj_head_kernel<<<dim3(12, 16), 128>>>(k, wk, 0, 1, S_, 1.0f);
    proj_head_kernel<<<dim3(12, 16), 128>>>(v, wv, 0, 2, S_, 1.0f);
    proj_head_kernel<<<dim3(12, 32), 128>>>(nullptr, w_rk, 1, 3, J_, 1.0f);

    bias_kernel<<<(H_ * S_ + 255) / 256, 256>>>(r_w, 0, S_);
    bias_kernel<<<(H_ * J_ + 255) / 256, 256>>>(r_r, 1, J_);

    logits_kernel<<<dim3(16, 16, 12), 256>>>(attn_ptr);

    softmax_kernel<<<H_ * S_, 256>>>(attn_ptr);

    if (need_out) {
        av_kernel<<<dim3(16, 12), 128>>>(attn_ptr);
        gemm_bias_kernel<<<dim3(12, 16), 128>>>(w_out, b_out, out_ptr);
    }
}

// round 6
// speedup vs baseline: 2.1833x; 1.2168x over previous
#include <cuda_runtime.h>
#include <math.h>

#define S_    2048
#define DM_   768
#define H_    12
#define DK_   64
#define FEAT_ 128
#define J_    4095   /* 2S-1 */

typedef unsigned long long u64;

__device__ __forceinline__ u64 pack2(float lo, float hi) {
    u64 r; asm("mov.b64 %0, {%1, %2};" : "=l"(r) : "f"(lo), "f"(hi)); return r;
}
__device__ __forceinline__ void unpack2(u64 v, float& lo, float& hi) {
    asm("mov.b64 {%0, %1}, %2;" : "=f"(lo), "=f"(hi) : "l"(v));
}
__device__ __forceinline__ void fma2(u64& d, u64 a, u64 b) {
    asm("fma.rn.f32x2 %0, %1, %2, %0;" : "+l"(d) : "l"(a), "l"(b));
}
__device__ __forceinline__ u64 fma2n(u64 a, u64 b, u64 c) {
    u64 d; asm("fma.rn.f32x2 %0, %1, %2, %3;" : "=l"(d) : "l"(a), "l"(b), "l"(c)); return d;
}

// ---------------- scratch (static device globals; referenced ONLY in device code) --
__device__ float g_qh[H_*S_*DK_];
__device__ float g_kh[H_*S_*DK_];
__device__ float g_vh[H_*S_*DK_];
__device__ float g_pe[J_*DM_];
__device__ float g_rk[H_*J_*DK_];
__device__ float g_bw[H_*S_];
__device__ float g_br[H_*J_];
__device__ float g_attn[H_*S_*S_];
__device__ float g_opre[4*S_*DM_];     // 4 split-k partials for AV
__device__ float g_bmax[2048];
__device__ float g_gmaxf;
__device__ float g_lnf[FEAT_];
__device__ float g_la[S_];

// ---------------- XLA-style f32 lgamma (Lanczos g=7), f32 dataflow via double ------
__device__ __forceinline__ float xla_lgammaf(float a) {
    const double C[8] = { 676.520368121885098567009190444019,
                        -1259.13921672240287047156078755283,
                          771.3234287776530788486528258894,
                         -176.61502916214059906584551354,
                           12.507343278686904814458936853,
                           -0.13857109526572011689554707,
                            9.984369578019570859563e-6,
                            1.50563273514931155834e-7 };
    float z = a - 1.0f;
    float x = 1.0f;
    #pragma unroll
    for (int k = 0; k < 8; k++) {
        float ck    = (float)C[k];
        float denom = (float)((double)z + (double)(k + 1));
        float term  = (float)((double)ck / (double)denom);
        x = (float)((double)x + (double)term);
    }
    float t     = (float)(7.5 + (double)z);
    float zq    = (float)((double)z / 7.5);
    float l1p   = (float)log1p((double)zq);
    float log_t = (float)((double)((float)2.0149030205422647) + (double)l1p);
    float tol   = (float)((double)t / (double)log_t);
    float zp    = (float)((double)z + 0.5);
    float inner = (float)((double)zp - (double)tol);
    float prod  = (float)((double)inner * (double)log_t);
    float res   = (float)((double)((float)0.91893853320467274178) + (double)prod);
    float lx    = (float)log((double)x);
    return (float)((double)res + (double)lx);
}

__global__ void pe_const_kernel() {
    int i = blockIdx.x * blockDim.x + threadIdx.x;
    if (i < S_) g_la[i] = (i > 0) ? (float)log((double)i) : 0.0f;
    if (i < FEAT_) {
        float mean = 16.0f * (float)(i + 1);
        float cdiv = mean / 8.0f;
        float conc = cdiv * cdiv;
        float rate = mean / 64.0f;
        float lg   = xla_lgammaf(conc);
        float lr   = (float)log((double)rate);
        float t2   = (float)((double)conc * (double)lr);
        g_lnf[i]   = (float)((double)lg - (double)t2);
    }
}

__global__ void pe_prob_kernel() {
    int idx = blockIdx.x * blockDim.x + threadIdx.x;
    float prob = 0.0f;
    if (idx < J_ * FEAT_) {
        int p = idx / FEAT_, f = idx % FEAT_;
        int ap = p - (S_ - 1); if (ap < 0) ap = -ap;
        if (ap > 0) {
            float mean = 16.0f * (float)(f + 1);
            float cdiv = mean / 8.0f;
            float conc = cdiv * cdiv;
            float rate = mean / 64.0f;
            float cm1  = conc - 1.0f;
            float apf  = (float)ap;
            float lu1  = (float)((double)cm1 * (double)g_la[ap]);
            float lu2  = (float)((double)rate * (double)apf);
            float lu   = (float)((double)lu1 - (double)lu2);
            float arg  = (float)((double)lu - (double)g_lnf[f]);
            prob = (float)exp((double)arg);
        }
        g_pe[p * DM_ + 512 + f] = prob;
    }
    __shared__ float red[256];
    red[threadIdx.x] = prob;
    __syncthreads();
    for (int off = 128; off > 0; off >>= 1) {
        if (threadIdx.x < off) red[threadIdx.x] = fmaxf(red[threadIdx.x], red[threadIdx.x + off]);
        __syncthreads();
    }
    if (threadIdx.x == 0) g_bmax[blockIdx.x] = red[0];
}

__global__ void pe_max_kernel() {
    __shared__ float red[1024];
    int tid = threadIdx.x;
    red[tid] = fmaxf(g_bmax[tid], g_bmax[tid + 1024]);
    __syncthreads();
    for (int off = 512; off > 0; off >>= 1) {
        if (tid < off) red[tid] = fmaxf(red[tid], red[tid + off]);
        __syncthreads();
    }
    if (tid == 0) g_gmaxf = red[0];
}

__global__ void pe_fill_kernel() {
    int idx = blockIdx.x * blockDim.x + threadIdx.x;
    if (idx >= J_ * FEAT_) return;
    int p = idx / FEAT_, f = idx % FEAT_;
    int pos = p - (S_ - 1);
    float apos = (float)(pos < 0 ? -pos : pos);
    float sgn  = (pos > 0) ? 1.0f : (pos < 0 ? -1.0f : 0.0f);
    float step = (float)(8.0 / 127.0);
    float ex   = (float)(3.0 + (double)((float)((double)step * (double)f)));
    float hl   = (float)exp2((double)ex);
    float c    = (float)((double)(-(float)0.6931471805599453) / (double)hl);
    float arg  = (float)((double)c * (double)apos);
    float e1   = (float)exp((double)arg);
    float cw   = exp2f((float)(f + 1)) - 1.0f;
    float cm   = (cw > apos) ? 1.0f : 0.0f;
    float gam  = (float)((double)g_pe[p * DM_ + 512 + f] / (double)g_gmaxf);
    float* row = g_pe + (size_t)p * DM_;
    row[0   + f] = e1;
    row[128 + f] = e1 * sgn;
    row[256 + f] = cm;
    row[384 + f] = cm * sgn;
    row[512 + f] = gam;
    row[640 + f] = gam * sgn;
}

// ======== merged q/k/v projection: grid (12, 16, 3), z selects src/W/dst ===========
__global__ __launch_bounds__(128) void proj_qkv_kernel(
    const float* __restrict__ q, const float* __restrict__ k, const float* __restrict__ v,
    const float* __restrict__ wq, const float* __restrict__ wk, const float* __restrict__ wv)
{
    int z = blockIdx.z;
    const float* A = (z == 0) ? q : (z == 1) ? k : v;
    const float* W = (z == 0) ? wq : (z == 1) ? wk : wv;
    float* dst = (z == 0) ? g_qh : (z == 1) ? g_kh : g_vh;
    float scale = (z == 0) ? 0.125f : 1.0f;
    __shared__ float AsT[16 * 132];
    __shared__ float Ws[16 * 68];
    int r0 = blockIdx.y * 128, c0 = blockIdx.x * 64;
    int h  = c0 >> 6;
    int tid = threadIdx.x, tx = tid & 7, ty = tid >> 3;
    u64 acc[8][4];
    #pragma unroll
    for (int i = 0; i < 8; i++)
        #pragma unroll
        for (int j = 0; j < 4; j++) acc[i][j] = 0ull;
    int vo = 8 * tx + ((tx >= 4) ? 4 : 0);

    for (int kk = 0; kk < DM_; kk += 16) {
        __syncthreads();
        #pragma unroll
        for (int it = 0; it < 4; it++) {
            int lin = tid + it * 128;
            int r = lin >> 2, c4 = lin & 3;
            float4 val = *(const float4*)(A + (size_t)(r0 + r) * DM_ + kk + 4 * c4);
            AsT[(4 * c4 + 0) * 132 + r] = val.x;
            AsT[(4 * c4 + 1) * 132 + r] = val.y;
            AsT[(4 * c4 + 2) * 132 + r] = val.z;
            AsT[(4 * c4 + 3) * 132 + r] = val.w;
        }
        #pragma unroll
        for (int it = 0; it < 2; it++) {
            int lin = tid + it * 128;
            int kx = lin >> 4, c4 = lin & 15;
            float4 val = *(const float4*)(W + (size_t)(kk + kx) * DM_ + c0 + 4 * c4);
            int dd = 4 * c4 + ((c4 >= 8) ? 4 : 0);
            *(float4*)(Ws + kx * 68 + dd) = val;
        }
        __syncthreads();

        #pragma unroll 4
        for (int kx = 0; kx < 16; kx++) {
            float4 aa = *(const float4*)(AsT + kx * 132 + 8 * ty);
            float4 ab = *(const float4*)(AsT + kx * 132 + 8 * ty + 4);
            float4 wa = *(const float4*)(Ws + kx * 68 + vo);
            float4 wb = *(const float4*)(Ws + kx * 68 + vo + 4);
            u64 ap[8] = { pack2(aa.x, aa.x), pack2(aa.y, aa.y), pack2(aa.z, aa.z), pack2(aa.w, aa.w),
                          pack2(ab.x, ab.x), pack2(ab.y, ab.y), pack2(ab.z, ab.z), pack2(ab.w, ab.w) };
            u64 wp[4] = { pack2(wa.x, wa.y), pack2(wa.z, wa.w), pack2(wb.x, wb.y), pack2(wb.z, wb.w) };
            #pragma unroll
            for (int i = 0; i < 8; i++)
                #pragma unroll
                for (int j = 0; j < 4; j++) fma2(acc[i][j], ap[i], wp[j]);
        }
    }

    #pragma unroll
    for (int i = 0; i < 8; i++) {
        int r = r0 + 8 * ty + i;
        float ov[8];
        #pragma unroll
        for (int j = 0; j < 4; j++) unpack2(acc[i][j], ov[2 * j], ov[2 * j + 1]);
        float4 o0 = make_float4(ov[0] * scale, ov[1] * scale, ov[2] * scale, ov[3] * scale);
        float4 o1 = make_float4(ov[4] * scale, ov[5] * scale, ov[6] * scale, ov[7] * scale);
        float* dp = dst + ((size_t)h * S_ + r) * DK_ + 8 * tx;
        *(float4*)dp = o0;
        *(float4*)(dp + 4) = o1;
    }
}

// ======== rk projection: g_pe[4095,768] @ w_rk -> g_rk[h][4095][64] ================
__global__ __launch_bounds__(128) void proj_rk_kernel(const float* __restrict__ W)
{
    __shared__ float AsT[16 * 132];
    __shared__ float Ws[16 * 68];
    int r0 = blockIdx.y * 128, c0 = blockIdx.x * 64;
    int h  = c0 >> 6;
    int tid = threadIdx.x, tx = tid & 7, ty = tid >> 3;
    u64 acc[8][4];
    #pragma unroll
    for (int i = 0; i < 8; i++)
        #pragma unroll
        for (int j = 0; j < 4; j++) acc[i][j] = 0ull;
    int vo = 8 * tx + ((tx >= 4) ? 4 : 0);

    for (int kk = 0; kk < DM_; kk += 16) {
        __syncthreads();
        #pragma unroll
        for (int it = 0; it < 4; it++) {
            int lin = tid + it * 128;
            int r = lin >> 2, c4 = lin & 3;
            float4 val = make_float4(0.f, 0.f, 0.f, 0.f);
            if (r0 + r < J_)
                val = *(const float4*)(g_pe + (size_t)(r0 + r) * DM_ + kk + 4 * c4);
            AsT[(4 * c4 + 0) * 132 + r] = val.x;
            AsT[(4 * c4 + 1) * 132 + r] = val.y;
            AsT[(4 * c4 + 2) * 132 + r] = val.z;
            AsT[(4 * c4 + 3) * 132 + r] = val.w;
        }
        #pragma unroll
        for (int it = 0; it < 2; it++) {
            int lin = tid + it * 128;
            int kx = lin >> 4, c4 = lin & 15;
            float4 val = *(const float4*)(W + (size_t)(kk + kx) * DM_ + c0 + 4 * c4);
            int dd = 4 * c4 + ((c4 >= 8) ? 4 : 0);
            *(float4*)(Ws + kx * 68 + dd) = val;
        }
        __syncthreads();

        #pragma unroll 4
        for (int kx = 0; kx < 16; kx++) {
            float4 aa = *(const float4*)(AsT + kx * 132 + 8 * ty);
            float4 ab = *(const float4*)(AsT + kx * 132 + 8 * ty + 4);
            float4 wa = *(const float4*)(Ws + kx * 68 + vo);
            float4 wb = *(const float4*)(Ws + kx * 68 + vo + 4);
            u64 ap[8] = { pack2(aa.x, aa.x), pack2(aa.y, aa.y), pack2(aa.z, aa.z), pack2(aa.w, aa.w),
                          pack2(ab.x, ab.x), pack2(ab.y, ab.y), pack2(ab.z, ab.z), pack2(ab.w, ab.w) };
            u64 wp[4] = { pack2(wa.x, wa.y), pack2(wa.z, wa.w), pack2(wb.x, wb.y), pack2(wb.z, wb.w) };
            #pragma unroll
            for (int i = 0; i < 8; i++)
                #pragma unroll
                for (int j = 0; j < 4; j++) fma2(acc[i][j], ap[i], wp[j]);
        }
    }

    #pragma unroll
    for (int i = 0; i < 8; i++) {
        int r = r0 + 8 * ty + i;
        if (r >= J_) continue;
        float ov[8];
        #pragma unroll
        for (int j = 0; j < 4; j++) unpack2(acc[i][j], ov[2 * j], ov[2 * j + 1]);
        float* dp = g_rk + ((size_t)h * J_ + r) * DK_ + 8 * tx;
        *(float4*)dp       = make_float4(ov[0], ov[1], ov[2], ov[3]);
        *(float4*)(dp + 4) = make_float4(ov[4], ov[5], ov[6], ov[7]);
    }
}

// ======== output GEMM: g_opre[2048,768] @ W + bias -> dst row-major ================
__global__ __launch_bounds__(128) void gemm_bias_kernel(
    const float* __restrict__ W, const float* __restrict__ bias, float* __restrict__ dst)
{
    __shared__ float AsT[16 * 132];
    __shared__ float Ws[16 * 68];
    int r0 = blockIdx.y * 128, c0 = blockIdx.x * 64;
    int tid = threadIdx.x, tx = tid & 7, ty = tid >> 3;
    u64 acc[8][4];
    #pragma unroll
    for (int i = 0; i < 8; i++)
        #pragma unroll
        for (int j = 0; j < 4; j++) acc[i][j] = 0ull;
    int vo = 8 * tx + ((tx >= 4) ? 4 : 0);

    for (int kk = 0; kk < DM_; kk += 16) {
        __syncthreads();
        #pragma unroll
        for (int it = 0; it < 4; it++) {
            int lin = tid + it * 128;
            int r = lin >> 2, c4 = lin & 3;
            float4 val = *(const float4*)(g_opre + (size_t)(r0 + r) * DM_ + kk + 4 * c4);
            AsT[(4 * c4 + 0) * 132 + r] = val.x;
            AsT[(4 * c4 + 1) * 132 + r] = val.y;
            AsT[(4 * c4 + 2) * 132 + r] = val.z;
            AsT[(4 * c4 + 3) * 132 + r] = val.w;
        }
        #pragma unroll
        for (int it = 0; it < 2; it++) {
            int lin = tid + it * 128;
            int kx = lin >> 4, c4 = lin & 15;
            float4 val = *(const float4*)(W + (size_t)(kk + kx) * DM_ + c0 + 4 * c4);
            int dd = 4 * c4 + ((c4 >= 8) ? 4 : 0);
            *(float4*)(Ws + kx * 68 + dd) = val;
        }
        __syncthreads();

        #pragma unroll 4
        for (int kx = 0; kx < 16; kx++) {
            float4 aa = *(const float4*)(AsT + kx * 132 + 8 * ty);
            float4 ab = *(const float4*)(AsT + kx * 132 + 8 * ty + 4);
            float4 wa = *(const float4*)(Ws + kx * 68 + vo);
            float4 wb = *(const float4*)(Ws + kx * 68 + vo + 4);
            u64 ap[8] = { pack2(aa.x, aa.x), pack2(aa.y, aa.y), pack2(aa.z, aa.z), pack2(aa.w, aa.w),
                          pack2(ab.x, ab.x), pack2(ab.y, ab.y), pack2(ab.z, ab.z), pack2(ab.w, ab.w) };
            u64 wp[4] = { pack2(wa.x, wa.y), pack2(wa.z, wa.w), pack2(wb.x, wb.y), pack2(wb.z, wb.w) };
            #pragma unroll
            for (int i = 0; i < 8; i++)
                #pragma unroll
                for (int j = 0; j < 4; j++) fma2(acc[i][j], ap[i], wp[j]);
        }
    }

    float4 b0 = *(const float4*)(bias + c0 + 8 * tx);
    float4 b1 = *(const float4*)(bias + c0 + 8 * tx + 4);
    #pragma unroll
    for (int i = 0; i < 8; i++) {
        int r = r0 + 8 * ty + i;
        float ov[8];
        #pragma unroll
        for (int j = 0; j < 4; j++) unpack2(acc[i][j], ov[2 * j], ov[2 * j + 1]);
        float4 o0 = make_float4(ov[0] + b0.x, ov[1] + b0.y, ov[2] + b0.z, ov[3] + b0.w);
        float4 o1 = make_float4(ov[4] + b1.x, ov[5] + b1.y, ov[6] + b1.z, ov[7] + b1.w);
        float* dp = dst + (size_t)r * DM_ + c0 + 8 * tx;
        *(float4*)dp = o0;
        *(float4*)(dp + 4) = o1;
    }
}

// ---------------- bias vectors ------------------------------------------------------
__global__ void bias_kernel(const float* __restrict__ rvec, int mat_sel, int M)
{
    int idx = blockIdx.x * blockDim.x + threadIdx.x;
    if (idx >= H_ * M) return;
    const float* mat = mat_sel ? g_rk : g_kh;
    float* out = mat_sel ? g_br : g_bw;
    int h = idx / M, t = idx % M;
    const float* r = rvec + h * DK_;
    const float* m = mat + ((size_t)h * M + t) * DK_;
    float s = 0.0f;
    #pragma unroll
    for (int d = 0; d < DK_; d++) s += r[d] * m[d];
    out[idx] = s;
}

// ======== fused logits (unchanged from R5) ==========================================
__global__ __launch_bounds__(256) void logits_kernel(float* __restrict__ attn_arg)
{
    __shared__ float qsT[16 * 132];
    __shared__ float ksT[16 * 132];
    __shared__ float rs [16 * 256];
    __shared__ float bwS[128];
    __shared__ float brS[256];
    float* attn = attn_arg ? attn_arg : g_attn;
    int h = blockIdx.z, t0 = blockIdx.x * 128, s0 = blockIdx.y * 128;
    int tid = threadIdx.x, tx = tid & 15, ty = tid >> 4;

    const float* qb = g_qh + ((size_t)h * S_ + s0) * DK_;
    const float* kb = g_kh + ((size_t)h * S_ + t0) * DK_;
    int jbase = t0 - s0 + 1920;
    const float* rb = g_rk + ((size_t)h * J_ + jbase) * DK_;

    if (tid < 128) bwS[tid] = g_bw[h * S_ + t0 + tid];
    if (tid < 255) brS[tid] = g_br[h * J_ + jbase + tid];

    u64 acc[8][4];
    #pragma unroll
    for (int i = 0; i < 8; i++)
        #pragma unroll
        for (int j = 0; j < 4; j++) acc[i][j] = 0ull;

    int rb0 = 8 * (tx - ty) + 120;

    for (int phase = 0; phase < 4; phase++) {
        int dbase = phase * 16;
        __syncthreads();
        #pragma unroll
        for (int it = 0; it < 4; it++) {
            int lin = tid + it * 256;
            int m = lin >> 9;
            int l2 = lin & 511;
            int r = l2 >> 2, c4 = l2 & 3;
            const float* src = (m ? kb : qb) + (size_t)r * DK_ + dbase + 4 * c4;
            float4 val = *(const float4*)src;
            float* dstm = m ? ksT : qsT;
            dstm[(4 * c4 + 0) * 132 + r] = val.x;
            dstm[(4 * c4 + 1) * 132 + r] = val.y;
            dstm[(4 * c4 + 2) * 132 + r] = val.z;
            dstm[(4 * c4 + 3) * 132 + r] = val.w;
        }
        #pragma unroll
        for (int it = 0; it < 4; it++) {
            int lin = tid + it * 256;
            if (lin < 1020) {
                int jl = lin >> 2, c4 = lin & 3;
                float4 val = *(const float4*)(rb + (size_t)jl * DK_ + dbase + 4 * c4);
                rs[(4 * c4 + 0) * 256 + jl] = val.x;
                rs[(4 * c4 + 1) * 256 + jl] = val.y;
                rs[(4 * c4 + 2) * 256 + jl] = val.z;
                rs[(4 * c4 + 3) * 256 + jl] = val.w;
            }
        }
        __syncthreads();

        #pragma unroll 2
        for (int dl = 0; dl < 16; dl++) {
            float4 qa = *(const float4*)(qsT + dl * 132 + 8 * ty);
            float4 qb4 = *(const float4*)(qsT + dl * 132 + 8 * ty + 4);
            float4 ka = *(const float4*)(ksT + dl * 132 + 8 * tx);
            float4 kb4 = *(const float4*)(ksT + dl * 132 + 8 * tx + 4);
            const float* rp = rs + dl * 256 + rb0;
            float4 r0 = *(const float4*)(rp);
            float4 r1 = *(const float4*)(rp + 4);
            float4 r2 = *(const float4*)(rp + 8);
            float4 r3 = *(const float4*)(rp + 12);
            float rw[16] = { r0.x, r0.y, r0.z, r0.w, r1.x, r1.y, r1.z, r1.w,
                             r2.x, r2.y, r2.z, r2.w, r3.x, r3.y, r3.z, r3.w };
            u64 qq[8] = { pack2(qa.x, qa.x), pack2(qa.y, qa.y), pack2(qa.z, qa.z), pack2(qa.w, qa.w),
                          pack2(qb4.x, qb4.x), pack2(qb4.y, qb4.y), pack2(qb4.z, qb4.z), pack2(qb4.w, qb4.w) };
            u64 kp[4] = { pack2(ka.x, ka.y), pack2(ka.z, ka.w), pack2(kb4.x, kb4.y), pack2(kb4.z, kb4.w) };
            u64 E[7], O[7];
            #pragma unroll
            for (int vv = 0; vv < 7; vv++) {
                E[vv] = pack2(rw[2 * vv], rw[2 * vv + 1]);
                O[vv] = pack2(rw[2 * vv + 1], rw[2 * vv + 2]);
            }
            #pragma unroll
            for (int i = 0; i < 8; i++) {
                int eb = (7 - i) >> 1;
                #pragma unroll
                for (int j = 0; j < 4; j++) {
                    fma2(acc[i][j], qq[i], kp[j]);
                    fma2(acc[i][j], qq[i], (i & 1) ? E[j + eb] : O[j + eb]);
                }
            }
        }
    }

    #pragma unroll
    for (int i = 0; i < 8; i++) {
        int s_loc = 8 * ty + i;
        int s = s0 + s_loc;
        float ov[8];
        #pragma unroll
        for (int j = 0; j < 4; j++) unpack2(acc[i][j], ov[2 * j], ov[2 * j + 1]);
        #pragma unroll
        for (int jj = 0; jj < 8; jj++) {
            int tl = 8 * tx + jj;
            ov[jj] += bwS[tl] + brS[tl - s_loc + 127];
        }
        float* dp = attn + ((size_t)h * S_ + s) * S_ + t0 + 8 * tx;
        *(float4*)dp       = make_float4(ov[0], ov[1], ov[2], ov[3]);
        *(float4*)(dp + 4) = make_float4(ov[4], ov[5], ov[6], ov[7]);
    }
}

// ======== softmax: hybrid MUFU + f32x2-poly exp, shuffle reductions ================
__device__ __forceinline__ u64 exp2_pair(float ylo, float yhi) {
    const float MAG = 12582912.0f;             // 1.5 * 2^23
    u64 y2 = pack2(ylo, yhi);
    u64 mag2 = pack2(MAG, MAG);
    u64 t2; asm("add.rn.f32x2 %0, %1, %2;" : "=l"(t2) : "l"(y2), "l"(mag2));
    float tlo, thi; unpack2(t2, tlo, thi);
    int nlo = __float_as_int(tlo) - 0x4B400000;
    int nhi = __float_as_int(thi) - 0x4B400000;
    u64 negone = pack2(-1.0f, -1.0f);
    u64 u2 = fma2n(mag2, negone, t2);          // t - MAG  (rounded y)
    u64 f2 = fma2n(u2, negone, y2);            // y - n  in [-0.5, 0.5]
    u64 p  = pack2(1.3333558146428443e-3f, 1.3333558146428443e-3f);
    p = fma2n(p, f2, pack2(9.618129107628477e-3f, 9.618129107628477e-3f));
    p = fma2n(p, f2, pack2(5.550410866482158e-2f, 5.550410866482158e-2f));
    p = fma2n(p, f2, pack2(2.402265069591007e-1f, 2.402265069591007e-1f));
    p = fma2n(p, f2, pack2(6.931471805599453e-1f, 6.931471805599453e-1f));
    p = fma2n(p, f2, pack2(1.0f, 1.0f));
    float plo, phi; unpack2(p, plo, phi);
    int rlo = __float_as_int(plo) + (nlo << 23);
    int rhi = __float_as_int(phi) + (nhi << 23);
    return pack2(__int_as_float(rlo), __int_as_float(rhi));
}

__global__ __launch_bounds__(256) void softmax_kernel(float* __restrict__ attn_arg)
{
    float* attn = attn_arg ? attn_arg : g_attn;
    float* x = attn + (size_t)blockIdx.x * S_;
    int tid = threadIdx.x;
    float4 a = *(const float4*)(x + 8 * tid);
    float4 b = *(const float4*)(x + 8 * tid + 4);
    float m = fmaxf(fmaxf(fmaxf(a.x, a.y), fmaxf(a.z, a.w)),
                    fmaxf(fmaxf(b.x, b.y), fmaxf(b.z, b.w)));
    __shared__ float red[8];
    #pragma unroll
    for (int off = 16; off; off >>= 1) m = fmaxf(m, __shfl_xor_sync(0xffffffffu, m, off));
    if ((tid & 31) == 0) red[tid >> 5] = m;
    __syncthreads();
    float mm = red[0];
    #pragma unroll
    for (int j = 1; j < 8; j++) mm = fmaxf(mm, red[j]);

    const float L2E = 1.4426950408889634f;
    float nm = -mm * L2E;
    float y0 = fmaf(a.x, L2E, nm), y1 = fmaf(a.y, L2E, nm);
    float y2 = fmaf(a.z, L2E, nm), y3 = fmaf(a.w, L2E, nm);
    float y4 = fmaf(b.x, L2E, nm), y5 = fmaf(b.y, L2E, nm);
    float y6 = fmaf(b.z, L2E, nm), y7 = fmaf(b.w, L2E, nm);

    float e0, e1, e2, e3;
    asm("ex2.approx.f32 %0, %1;" : "=f"(e0) : "f"(y0));
    asm("ex2.approx.f32 %0, %1;" : "=f"(e1) : "f"(y1));
    asm("ex2.approx.f32 %0, %1;" : "=f"(e2) : "f"(y2));
    asm("ex2.approx.f32 %0, %1;" : "=f"(e3) : "f"(y3));
    u64 r45 = exp2_pair(fmaxf(y4, -125.0f), fmaxf(y5, -125.0f));
    u64 r67 = exp2_pair(fmaxf(y6, -125.0f), fmaxf(y7, -125.0f));
    float e4, e5, e6, e7;
    unpack2(r45, e4, e5);
    unpack2(r67, e6, e7);

    float sum = ((e0 + e1) + (e2 + e3)) + ((e4 + e5) + (e6 + e7));
    #pragma unroll
    for (int off = 16; off; off >>= 1) sum += __shfl_xor_sync(0xffffffffu, sum, off);
    __syncthreads();
    if ((tid & 31) == 0) red[tid >> 5] = sum;
    __syncthreads();
    float ss = red[0];
    #pragma unroll
    for (int j = 1; j < 8; j++) ss += red[j];
    float inv = 1.0f / ss;

    *(float4*)(x + 8 * tid)     = make_float4(e0 * inv, e1 * inv, e2 * inv, e3 * inv);
    *(float4*)(x + 8 * tid + 4) = make_float4(e4 * inv, e5 * inv, e6 * inv, e7 * inv);
}

// ======== attn @ V split-k: grid (16, 12, 4), partial sums into g_opre[z] ==========
__global__ __launch_bounds__(128) void av_kernel(const float* __restrict__ attn_arg)
{
    const float* attn = attn_arg ? attn_arg : (const float*)g_attn;
    __shared__ float AsT[16 * 132];
    __shared__ float Vs[16 * 68];
    int s0 = blockIdx.x * 128, h = blockIdx.y, z = blockIdx.z;
    int tid = threadIdx.x, tx = tid & 7, ty = tid >> 3;
    const float* ab = attn + ((size_t)h * S_ + s0) * S_;
    const float* vb = g_vh + (size_t)h * S_ * DK_;
    u64 acc[8][4];
    #pragma unroll
    for (int i = 0; i < 8; i++)
        #pragma unroll
        for (int j = 0; j < 4; j++) acc[i][j] = 0ull;
    int vo = 8 * tx + ((tx >= 4) ? 4 : 0);

    int k0 = z * 512, k1 = k0 + 512;
    for (int kk = k0; kk < k1; kk += 16) {
        __syncthreads();
        #pragma unroll
        for (int it = 0; it < 4; it++) {
            int lin = tid + it * 128;
            int s = lin >> 2, c4 = lin & 3;
            float4 val = *(const float4*)(ab + (size_t)s * S_ + kk + 4 * c4);
            AsT[(4 * c4 + 0) * 132 + s] = val.x;
            AsT[(4 * c4 + 1) * 132 + s] = val.y;
            AsT[(4 * c4 + 2) * 132 + s] = val.z;
            AsT[(4 * c4 + 3) * 132 + s] = val.w;
        }
        #pragma unroll
        for (int it = 0; it < 2; it++) {
            int lin = tid + it * 128;
            int kx = lin >> 4, c4 = lin & 15;
            float4 val = *(const float4*)(vb + (size_t)(kk + kx) * DK_ + 4 * c4);
            int dd = 4 * c4 + ((c4 >= 8) ? 4 : 0);
            *(float4*)(Vs + kx * 68 + dd) = val;
        }
        __syncthreads();

        #pragma unroll 4
        for (int kx = 0; kx < 16; kx++) {
            float4 aa = *(const float4*)(AsT + kx * 132 + 8 * ty);
            float4 ab4 = *(const float4*)(AsT + kx * 132 + 8 * ty + 4);
            float4 va = *(const float4*)(Vs + kx * 68 + vo);
            float4 vb4 = *(const float4*)(Vs + kx * 68 + vo + 4);
            u64 ap[8] = { pack2(aa.x, aa.x), pack2(aa.y, aa.y), pack2(aa.z, aa.z), pack2(aa.w, aa.w),
                          pack2(ab4.x, ab4.x), pack2(ab4.y, ab4.y), pack2(ab4.z, ab4.z), pack2(ab4.w, ab4.w) };
            u64 vp[4] = { pack2(va.x, va.y), pack2(va.z, va.w), pack2(vb4.x, vb4.y), pack2(vb4.z, vb4.w) };
            #pragma unroll
            for (int i = 0; i < 8; i++)
                #pragma unroll
                for (int j = 0; j < 4; j++) fma2(acc[i][j], ap[i], vp[j]);
        }
    }

    #pragma unroll
    for (int i = 0; i < 8; i++) {
        int s = s0 + 8 * ty + i;
        float ov[8];
        #pragma unroll
        for (int j = 0; j < 4; j++) unpack2(acc[i][j], ov[2 * j], ov[2 * j + 1]);
        float* dp = g_opre + ((size_t)z * S_ + s) * DM_ + h * DK_ + 8 * tx;
        *(float4*)dp       = make_float4(ov[0], ov[1], ov[2], ov[3]);
        *(float4*)(dp + 4) = make_float4(ov[4], ov[5], ov[6], ov[7]);
    }
}

// ---------------- combine 4 AV partials into partial 0 -----------------------------
__global__ __launch_bounds__(256) void combine_kernel()
{
    size_t idx = (size_t)blockIdx.x * blockDim.x + threadIdx.x;     // float4 index
    const size_t N = (size_t)S_ * DM_;
    float4 r0 = ((float4*)g_opre)[idx];
    float4 r1 = ((float4*)(g_opre + N))[idx];
    float4 r2 = ((float4*)(g_opre + 2 * N))[idx];
    float4 r3 = ((float4*)(g_opre + 3 * N))[idx];
    r0.x = (r0.x + r1.x) + (r2.x + r3.x);
    r0.y = (r0.y + r1.y) + (r2.y + r3.y);
    r0.z = (r0.z + r1.z) + (r2.z + r3.z);
    r0.w = (r0.w + r1.w) + (r2.w + r3.w);
    ((float4*)g_opre)[idx] = r0;
}

// ---------------- host launcher -----------------------------------------------------
extern "C" void kernel_launch(void* const* d_in, const int* in_sizes, int n_in,
                              void* d_out, int out_size)
{
    const int QKV = 1572864, WMAT = 589824, VEC = 768;
    const float *q, *k, *v, *wq, *wk, *wv, *w_rk, *r_w, *r_r, *w_out, *b_out;
    if (n_in >= 11 && in_sizes[0] == VEC && in_sizes[1] == QKV && in_sizes[5] == QKV
        && in_sizes[6] == WMAT) {
        b_out = (const float*)d_in[0];
        k     = (const float*)d_in[1];
        q     = (const float*)d_in[2];
        r_r   = (const float*)d_in[3];
        r_w   = (const float*)d_in[4];
        v     = (const float*)d_in[5];
        w_out = (const float*)d_in[6];
        w_rk  = (const float*)d_in[7];
        wk    = (const float*)d_in[8];
        wq    = (const float*)d_in[9];
        wv    = (const float*)d_in[10];
    } else {
        q     = (const float*)d_in[0];
        k     = (const float*)d_in[1];
        v     = (const float*)d_in[2];
        wq    = (const float*)d_in[3];
        wk    = (const float*)d_in[4];
        wv    = (const float*)d_in[5];
        w_rk  = (const float*)d_in[6];
        r_w   = (const float*)d_in[7];
        r_r   = (const float*)d_in[8];
        w_out = (const float*)d_in[9];
        b_out = (const float*)d_in[10];
    }

    const long long OUT_E  = (long long)S_ * DM_;
    const long long ATTN_E = (long long)H_ * S_ * S_;
    long long os = (long long)out_size;

    float* out_ptr  = (float*)d_out;
    float* attn_ptr = nullptr;
    bool need_out = true;

    if (os >= OUT_E + ATTN_E) {
        attn_ptr = (float*)d_out + OUT_E;
    } else if (os == ATTN_E) {
        attn_ptr = (float*)d_out;
        need_out = false;
    }

    pe_const_kernel<<<8, 256>>>();
    pe_prob_kernel<<<2048, 256>>>();
    pe_max_kernel<<<1, 1024>>>();
    pe_fill_kernel<<<2048, 256>>>();

    proj_qkv_kernel<<<dim3(12, 16, 3), 128>>>(q, k, v, wq, wk, wv);
    proj_rk_kernel<<<dim3(12, 32), 128>>>(w_rk);

    bias_kernel<<<(H_ * S_ + 255) / 256, 256>>>(r_w, 0, S_);
    bias_kernel<<<(H_ * J_ + 255) / 256, 256>>>(r_r, 1, J_);

    logits_kernel<<<dim3(16, 16, 12), 256>>>(attn_ptr);

    softmax_kernel<<<H_ * S_, 256>>>(attn_ptr);

    if (need_out) {
        av_kernel<<<dim3(16, 12, 4), 128>>>(attn_ptr);
        combine_kernel<<<1536, 256>>>();
        gemm_bias_kernel<<<dim3(12, 16), 128>>>(w_out, b_out, out_ptr);
    }
}